// round 12
// baseline (speedup 1.0000x reference)
#include <cuda_runtime.h>
#include <cstdint>

// out[i] = 0.5 * sum_{bonds b with adj[b,0]==i} par[b] * (|xyz[a0]-xyz[a1]| - len[b])^2
// bond_adj arrives as int32 (JAX x64-disabled downcasts int64).
//
// L2-sector-roofline design (~28M sector-ops ≈ 79us floor for main kernel):
//  - xyz repacked to float4 (1 LDG.128 = 1 sector per endpoint gather)
//  - zero_out fused into repack (one prep launch)
//  - 2 bonds/thread, regs<=32, 8 CTAs/SM -> 100% occupancy to saturate LTS.

#define MAX_ATOMS 2000000
__device__ float4 g_xyz4[MAX_ATOMS];   // 32 MB static scratch

// Fused: zero output + repack xyz [N,3] -> float4 table
__global__ void __launch_bounds__(256)
prep_kernel(const float* __restrict__ xyz, float* __restrict__ out, int natoms)
{
    int i = blockIdx.x * blockDim.x + threadIdx.x;
    if (i >= natoms) return;
    out[i] = 0.0f;
    const float* p = xyz + (size_t)i * 3;
    float4 v;
    v.x = __ldg(p + 0);
    v.y = __ldg(p + 1);
    v.z = __ldg(p + 2);
    v.w = 0.0f;
    g_xyz4[i] = v;
}

__device__ __forceinline__ float bond_e(float4 a, float4 b, float len, float par)
{
    float dx = a.x - b.x;
    float dy = a.y - b.y;
    float dz = a.z - b.z;
    float d  = sqrtf(fmaf(dx, dx, fmaf(dy, dy, dz * dz)));
    float t  = d - len;
    return 0.5f * par * t * t;
}

// 2 bonds per thread, forced 8 CTAs/SM (caps regs at 32 -> 100% occupancy)
__global__ void __launch_bounds__(256, 8)
bond_energy_kernel(const int4*   __restrict__ adj2,  // [E/2]: two pairs per int4
                   const float2* __restrict__ blen2, // [E/2]
                   const float2* __restrict__ bpar2, // [E/2]
                   float* __restrict__ out,          // [N]
                   int npairs)                       // E/2
{
    int p = blockIdx.x * blockDim.x + threadIdx.x;
    if (p >= npairs) return;

    int4   ij  = __ldg(adj2 + p);    // (i0,j0,i1,j1)
    float2 len = __ldg(blen2 + p);
    float2 par = __ldg(bpar2 + p);

    // 4 independent gathers in flight before any FP work
    float4 a0 = __ldg(&g_xyz4[ij.x]);
    float4 b0 = __ldg(&g_xyz4[ij.y]);
    float4 a1 = __ldg(&g_xyz4[ij.z]);
    float4 b1 = __ldg(&g_xyz4[ij.w]);

    atomicAdd(out + ij.x, bond_e(a0, b0, len.x, par.x));
    atomicAdd(out + ij.z, bond_e(a1, b1, len.y, par.y));
}

// Tail for odd bond counts
__global__ void __launch_bounds__(128)
bond_energy_tail_kernel(const int2*  __restrict__ adj,
                        const float* __restrict__ blen,
                        const float* __restrict__ bpar,
                        float* __restrict__ out,
                        int start, int nbonds)
{
    int e = start + blockIdx.x * blockDim.x + threadIdx.x;
    if (e >= nbonds) return;
    int2 ij = __ldg(adj + e);
    float4 a = __ldg(&g_xyz4[ij.x]);
    float4 b = __ldg(&g_xyz4[ij.y]);
    atomicAdd(out + ij.x, bond_e(a, b, __ldg(blen + e), __ldg(bpar + e)));
}

extern "C" void kernel_launch(void* const* d_in, const int* in_sizes, int n_in,
                              void* d_out, int out_size)
{
    const float* xyz  = (const float*)d_in[0];  // [N,3]
    const int2*  adj  = (const int2*)d_in[1];   // [E,2] int32
    const float* blen = (const float*)d_in[2];  // [E,1]
    const float* bpar = (const float*)d_in[3];  // [E,1]
    float*       out  = (float*)d_out;          // [N,1]

    int nbonds = in_sizes[1] / 2;
    int natoms = out_size;
    int npairs = nbonds / 2;
    int tail   = npairs * 2;

    {
        int threads = 256;
        prep_kernel<<<(natoms + threads - 1) / threads, threads>>>(xyz, out, natoms);
    }
    if (npairs > 0) {
        int threads = 256;
        bond_energy_kernel<<<(npairs + threads - 1) / threads, threads>>>(
            (const int4*)adj, (const float2*)blen, (const float2*)bpar, out, npairs);
    }
    if (tail < nbonds) {
        int threads = 128;
        int n = nbonds - tail;
        bond_energy_tail_kernel<<<(n + threads - 1) / threads, threads>>>(
            adj, blen, bpar, out, tail, nbonds);
    }
}